// round 1
// baseline (speedup 1.0000x reference)
#include <cuda_runtime.h>
#include <math.h>

// Problem constants (fixed shapes for this problem instance)
#define N_TOT 200000
#define D_DIM 128
#define T_DIM 8
#define P_DIM 2000
#define NP_DIM 9
#define H_DIM 2048
#define PT (P_DIM * T_DIM)          // 16000 segments
#define TD (T_DIM * D_DIM)          // 1024 = K of GEMM1

// ---------------- scratch (device globals; no cudaMalloc allowed) ----------
__device__ float g_pt_sum[PT * D_DIM];     // [P*T, D] masked sums
__device__ float g_pt_cnt[PT];             // [P*T]
__device__ float g_task_mean[TD];          // [T, D]
__device__ int   g_first[P_DIM];           // first valid row per patient
__device__ float g_fp[P_DIM * TD];         // fingerprint [P, 1024]
__device__ float g_h1[P_DIM * H_DIM];      // relu(fp@W1+b1)
__device__ float g_h2[P_DIM * H_DIM];      // relu(h1@W2+b2)

// ---------------- K0: init accumulators ------------------------------------
__global__ void k_init() {
    int i = blockIdx.x * blockDim.x + threadIdx.x;
    int stride = gridDim.x * blockDim.x;
    for (int j = i; j < PT * D_DIM; j += stride) g_pt_sum[j] = 0.0f;
    for (int j = i; j < PT; j += stride) g_pt_cnt[j] = 0.0f;
    for (int j = i; j < P_DIM; j += stride) g_first[j] = N_TOT;
}

// ---------------- K1: masked scatter (one warp per row) --------------------
__global__ void k_scatter(const float* __restrict__ motion_z,
                          const int* __restrict__ tasks,
                          const int* __restrict__ tasks_mask,
                          const int* __restrict__ patient_ids,
                          const int* __restrict__ phenos_mask) {
    int warp_id = (blockIdx.x * blockDim.x + threadIdx.x) >> 5;
    int lane = threadIdx.x & 31;
    if (warp_id >= N_TOT) return;

    // all lanes read the same scalars (broadcast via L1)
    int tm = tasks_mask[warp_id];
    int pm = phenos_mask[warp_id];
    if (tm != 1 || pm != 1) return;

    int t = tasks[warp_id];
    int p = patient_ids[warp_id];
    int seg = p * T_DIM + t;

    // 32 lanes x float4 = 128 floats
    const float4* src = reinterpret_cast<const float4*>(motion_z + (size_t)warp_id * D_DIM);
    float4 v = src[lane];
    float* dst = g_pt_sum + (size_t)seg * D_DIM + lane * 4;
    atomicAdd(dst + 0, v.x);
    atomicAdd(dst + 1, v.y);
    atomicAdd(dst + 2, v.z);
    atomicAdd(dst + 3, v.w);
    if (lane == 0) {
        atomicAdd(&g_pt_cnt[seg], 1.0f);
        atomicMin(&g_first[p], warp_id);
    }
}

// ---------------- K2a: per-task mean (reduce pt accumulator) ---------------
// one block per task t, 128 threads (one per d)
__global__ void k_task_mean() {
    int t = blockIdx.x;
    int d = threadIdx.x;
    __shared__ float scnt[128];

    float c = 0.0f;
    for (int p = d; p < P_DIM; p += 128) c += g_pt_cnt[p * T_DIM + t];
    scnt[d] = c;
    __syncthreads();
    for (int s = 64; s > 0; s >>= 1) {
        if (d < s) scnt[d] += scnt[d + s];
        __syncthreads();
    }
    float tc = fmaxf(scnt[0], 1.0f);

    float sum = 0.0f;
    for (int p = 0; p < P_DIM; p++)
        sum += g_pt_sum[((size_t)p * T_DIM + t) * D_DIM + d];
    g_task_mean[t * D_DIM + d] = sum / tc;
}

// ---------------- K2b: fingerprint [P, T*D] ---------------------------------
__global__ void k_fingerprint() {
    int idx = blockIdx.x * blockDim.x + threadIdx.x;     // over P*T*D
    if (idx >= PT * D_DIM) return;
    int seg = idx / D_DIM;           // p*T + t
    int d = idx - seg * D_DIM;
    int t = seg % T_DIM;
    float cnt = g_pt_cnt[seg];
    float v = (cnt > 0.0f) ? (g_pt_sum[idx] / cnt) : g_task_mean[t * D_DIM + d];
    g_fp[idx] = v;   // flat layout identical to fingerprint.reshape(P, T*D)
}

// ---------------- K2c: uni_phenos gather ------------------------------------
__global__ void k_uni_phenos(const float* __restrict__ phenos, float* __restrict__ out_uni) {
    int idx = blockIdx.x * blockDim.x + threadIdx.x;     // over P*NP
    if (idx >= P_DIM * NP_DIM) return;
    int p = idx / NP_DIM;
    int j = idx - p * NP_DIM;
    int f = g_first[p];
    if (f > N_TOT - 1) f = N_TOT - 1;   // clip (matches jnp.clip(first, 0, N-1))
    out_uni[idx] = phenos[(size_t)f * NP_DIM + j];
}

// ---------------- SGEMM: C = relu(A@B + bias) -------------------------------
// BM=BN=128, BK=8, 256 threads, 8x8 thread tile. K % 8 == 0, N % 128 == 0.
template <bool RELU>
__global__ __launch_bounds__(256) void k_sgemm_bias(
    int M, int N, int K,
    const float* __restrict__ A, const float* __restrict__ B,
    const float* __restrict__ bias, float* __restrict__ C) {
    const int BM = 128, BN = 128, BK = 8, TM = 8, TN = 8;
    __shared__ float As[BK * BM];   // transposed: As[k][m]
    __shared__ float Bs[BK * BN];

    int tid = threadIdx.x;
    int tx = tid % 16;              // 16 x 16 thread grid
    int ty = tid / 16;
    int blockM = blockIdx.y * BM;
    int blockN = blockIdx.x * BN;

    // A load mapping: each thread loads one float4 of the 128x8 A tile
    int aRow = tid / 2;             // 0..127
    int aCol = (tid % 2) * 4;       // 0 or 4
    // B load mapping: each thread loads one float4 of the 8x128 B tile
    int bRow = tid / 32;            // 0..7
    int bCol = (tid % 32) * 4;      // 0..124

    float acc[TM][TN];
#pragma unroll
    for (int i = 0; i < TM; i++)
#pragma unroll
        for (int j = 0; j < TN; j++) acc[i][j] = 0.0f;

    float regA[TM], regB[TN];

    for (int k0 = 0; k0 < K; k0 += BK) {
        // load A tile (guard M edge)
        float4 av = make_float4(0.f, 0.f, 0.f, 0.f);
        int gRow = blockM + aRow;
        if (gRow < M)
            av = *reinterpret_cast<const float4*>(A + (size_t)gRow * K + k0 + aCol);
        As[(aCol + 0) * BM + aRow] = av.x;
        As[(aCol + 1) * BM + aRow] = av.y;
        As[(aCol + 2) * BM + aRow] = av.z;
        As[(aCol + 3) * BM + aRow] = av.w;
        // load B tile
        float4 bv = *reinterpret_cast<const float4*>(B + (size_t)(k0 + bRow) * N + blockN + bCol);
        *reinterpret_cast<float4*>(&Bs[bRow * BN + bCol]) = bv;
        __syncthreads();

#pragma unroll
        for (int k = 0; k < BK; k++) {
#pragma unroll
            for (int i = 0; i < TM; i++) regA[i] = As[k * BM + ty * TM + i];
#pragma unroll
            for (int j = 0; j < TN; j++) regB[j] = Bs[k * BN + tx * TN + j];
#pragma unroll
            for (int i = 0; i < TM; i++)
#pragma unroll
                for (int j = 0; j < TN; j++) acc[i][j] = fmaf(regA[i], regB[j], acc[i][j]);
        }
        __syncthreads();
    }

#pragma unroll
    for (int i = 0; i < TM; i++) {
        int row = blockM + ty * TM + i;
        if (row >= M) continue;
#pragma unroll
        for (int j = 0; j < TN; j++) {
            int col = blockN + tx * TN + j;
            float v = acc[i][j] + bias[col];
            if (RELU) v = fmaxf(v, 0.0f);
            C[(size_t)row * N + col] = v;
        }
    }
}

// ---------------- K5: latent = h@W3 + b3; out = sigmoid(latent) -------------
// one block (256 threads) per patient row
__global__ __launch_bounds__(256) void k_head(
    const float* __restrict__ h, const float* __restrict__ W3,
    const float* __restrict__ b3,
    float* __restrict__ out_sig, float* __restrict__ out_latent) {
    int p = blockIdx.x;
    int tid = threadIdx.x;
    int lane = tid & 31;
    int wid = tid >> 5;

    float acc[NP_DIM];
#pragma unroll
    for (int j = 0; j < NP_DIM; j++) acc[j] = 0.0f;

    const float* hrow = h + (size_t)p * H_DIM;
    for (int k = tid; k < H_DIM; k += 256) {
        float hv = hrow[k];
        const float* w = W3 + (size_t)k * NP_DIM;
#pragma unroll
        for (int j = 0; j < NP_DIM; j++) acc[j] = fmaf(hv, w[j], acc[j]);
    }
    // warp reduce
#pragma unroll
    for (int j = 0; j < NP_DIM; j++) {
#pragma unroll
        for (int s = 16; s > 0; s >>= 1)
            acc[j] += __shfl_down_sync(0xFFFFFFFF, acc[j], s);
    }
    __shared__ float smem[8][NP_DIM];
    if (lane == 0) {
#pragma unroll
        for (int j = 0; j < NP_DIM; j++) smem[wid][j] = acc[j];
    }
    __syncthreads();
    if (tid < NP_DIM) {
        float s = 0.0f;
#pragma unroll
        for (int w = 0; w < 8; w++) s += smem[w][tid];
        float latent = s + b3[tid];
        out_latent[p * NP_DIM + tid] = latent;
        out_sig[p * NP_DIM + tid] = 1.0f / (1.0f + expf(-latent));
    }
}

// ---------------- launch ----------------------------------------------------
extern "C" void kernel_launch(void* const* d_in, const int* in_sizes, int n_in,
                              void* d_out, int out_size) {
    const float* motion_z    = (const float*)d_in[0];
    const int*   tasks       = (const int*)d_in[1];
    const int*   tasks_mask  = (const int*)d_in[2];
    const int*   patient_ids = (const int*)d_in[3];
    const float* phenos      = (const float*)d_in[4];
    const int*   phenos_mask = (const int*)d_in[5];
    const float* W1          = (const float*)d_in[6];
    const float* b1          = (const float*)d_in[7];
    const float* W2          = (const float*)d_in[8];
    const float* b2          = (const float*)d_in[9];
    const float* W3          = (const float*)d_in[10];
    const float* b3          = (const float*)d_in[11];

    float* out_sig    = (float*)d_out;                          // [P, NP]
    float* out_uni    = out_sig + P_DIM * NP_DIM;               // [P, NP]
    float* out_latent = out_uni + P_DIM * NP_DIM;               // [P, NP]

    float* pt_sum;   cudaGetSymbolAddress((void**)&pt_sum, g_pt_sum);
    float* fp;       cudaGetSymbolAddress((void**)&fp, g_fp);
    float* h1;       cudaGetSymbolAddress((void**)&h1, g_h1);
    float* h2;       cudaGetSymbolAddress((void**)&h2, g_h2);
    (void)pt_sum;

    // K0 init
    k_init<<<1024, 256>>>();
    // K1 scatter: one warp per row -> N_TOT warps
    k_scatter<<<(N_TOT * 32 + 255) / 256, 256>>>(motion_z, tasks, tasks_mask,
                                                 patient_ids, phenos_mask);
    // K2a per-task means
    k_task_mean<<<T_DIM, 128>>>();
    // K2b fingerprint
    k_fingerprint<<<(PT * D_DIM + 255) / 256, 256>>>();
    // K2c uni_phenos
    k_uni_phenos<<<(P_DIM * NP_DIM + 255) / 256, 256>>>(phenos, out_uni);

    // GEMM1: [2000,1024] @ [1024,2048] -> h1 (relu)
    {
        dim3 grid(H_DIM / 128, (P_DIM + 127) / 128);
        k_sgemm_bias<true><<<grid, 256>>>(P_DIM, H_DIM, TD, fp, W1, b1, h1);
    }
    // GEMM2: [2000,2048] @ [2048,2048] -> h2 (relu)
    {
        dim3 grid(H_DIM / 128, (P_DIM + 127) / 128);
        k_sgemm_bias<true><<<grid, 256>>>(P_DIM, H_DIM, H_DIM, h1, W2, b2, h2);
    }
    // Head: latent + sigmoid
    k_head<<<P_DIM, 256>>>(h2, W3, b3, out_sig, out_latent);
}

// round 2
// speedup vs baseline: 2.7130x; 2.7130x over previous
#include <cuda_runtime.h>
#include <cuda_bf16.h>
#include <math.h>
#include <stdint.h>

// Problem constants
#define N_TOT 200000
#define D_DIM 128
#define T_DIM 8
#define P_DIM 2000
#define NP_DIM 9
#define H_DIM 2048
#define PT (P_DIM * T_DIM)
#define TD (T_DIM * D_DIM)          // 1024

// ---------------- scratch ----------------------------------------------------
__device__ float g_pt_sum[PT * D_DIM];
__device__ float g_pt_cnt[PT];
__device__ float g_task_mean[TD];
__device__ int   g_first[P_DIM];
__device__ float g_fp[P_DIM * TD];
__device__ float g_h1[P_DIM * H_DIM];
__device__ float g_h2[P_DIM * H_DIM];

// ---------------- K0: init ----------------------------------------------------
__global__ void k_init() {
    int i = blockIdx.x * blockDim.x + threadIdx.x;
    int stride = gridDim.x * blockDim.x;
    for (int j = i; j < PT * D_DIM; j += stride) g_pt_sum[j] = 0.0f;
    for (int j = i; j < PT; j += stride) g_pt_cnt[j] = 0.0f;
    for (int j = i; j < P_DIM; j += stride) g_first[j] = N_TOT;
}

// ---------------- K1: masked scatter (one warp per row) ------------------------
__global__ void k_scatter(const float* __restrict__ motion_z,
                          const int* __restrict__ tasks,
                          const int* __restrict__ tasks_mask,
                          const int* __restrict__ patient_ids,
                          const int* __restrict__ phenos_mask) {
    int warp_id = (blockIdx.x * blockDim.x + threadIdx.x) >> 5;
    int lane = threadIdx.x & 31;
    if (warp_id >= N_TOT) return;

    int tm = tasks_mask[warp_id];
    int pm = phenos_mask[warp_id];
    if (tm != 1 || pm != 1) return;

    int t = tasks[warp_id];
    int p = patient_ids[warp_id];
    int seg = p * T_DIM + t;

    const float4* src = reinterpret_cast<const float4*>(motion_z + (size_t)warp_id * D_DIM);
    float4 v = src[lane];
    float* dst = g_pt_sum + (size_t)seg * D_DIM + lane * 4;
    atomicAdd(dst + 0, v.x);
    atomicAdd(dst + 1, v.y);
    atomicAdd(dst + 2, v.z);
    atomicAdd(dst + 3, v.w);
    if (lane == 0) {
        atomicAdd(&g_pt_cnt[seg], 1.0f);
        atomicMin(&g_first[p], warp_id);
    }
}

// ---------------- K2a: per-task mean -------------------------------------------
__global__ void k_task_mean() {
    int t = blockIdx.x;
    int d = threadIdx.x;
    __shared__ float scnt[128];

    float c = 0.0f;
    for (int p = d; p < P_DIM; p += 128) c += g_pt_cnt[p * T_DIM + t];
    scnt[d] = c;
    __syncthreads();
    for (int s = 64; s > 0; s >>= 1) {
        if (d < s) scnt[d] += scnt[d + s];
        __syncthreads();
    }
    float tc = fmaxf(scnt[0], 1.0f);

    float sum = 0.0f;
    for (int p = 0; p < P_DIM; p++)
        sum += g_pt_sum[((size_t)p * T_DIM + t) * D_DIM + d];
    g_task_mean[t * D_DIM + d] = sum / tc;
}

// ---------------- K2b: fingerprint ----------------------------------------------
__global__ void k_fingerprint() {
    int idx = blockIdx.x * blockDim.x + threadIdx.x;
    if (idx >= PT * D_DIM) return;
    int seg = idx / D_DIM;
    int d = idx - seg * D_DIM;
    int t = seg % T_DIM;
    float cnt = g_pt_cnt[seg];
    float v = (cnt > 0.0f) ? (g_pt_sum[idx] / cnt) : g_task_mean[t * D_DIM + d];
    g_fp[idx] = v;
}

// ---------------- K2c: uni_phenos gather ----------------------------------------
__global__ void k_uni_phenos(const float* __restrict__ phenos, float* __restrict__ out_uni) {
    int idx = blockIdx.x * blockDim.x + threadIdx.x;
    if (idx >= P_DIM * NP_DIM) return;
    int p = idx / NP_DIM;
    int j = idx - p * NP_DIM;
    int f = g_first[p];
    if (f > N_TOT - 1) f = N_TOT - 1;
    out_uni[idx] = phenos[(size_t)f * NP_DIM + j];
}

// =================================================================================
// Split-bf16 tensor-core GEMM: C = relu(A@B + bias)
// A [M,K] fp32 row-major, B [K,N] fp32 row-major. K%32==0, N%128==0.
// Each fp32 x split into hi+lo bf16; acc += ahi*bhi + ahi*blo + alo*bhi (fp32 acc).
// Block tile 128x128, BK=32, 256 threads (8 warps as 2x4), warp tile 64x32.
// =================================================================================

// smem element offsets (bf16 units) within one stage
#define A_STRIDE 40      // 128 rows x 40 (pad 8) -> 80B row, stride16=5 (odd)
#define B_STRIDE 136     // 32 rows x 136 (pad 8) -> 272B row, stride16=17 (odd)
#define SM_A_HI 0
#define SM_A_LO (128 * A_STRIDE)                 // 5120
#define SM_B_HI (2 * 128 * A_STRIDE)             // 10240
#define SM_B_LO (2 * 128 * A_STRIDE + 32 * B_STRIDE)   // 14592
#define STAGE_ELTS (2 * 128 * A_STRIDE + 2 * 32 * B_STRIDE)  // 18944 elts
#define SMEM_BYTES (2 * STAGE_ELTS * 2)          // 75776 bytes

__device__ __forceinline__ void ldsm_x4(uint32_t* r, uint32_t addr) {
    asm volatile("ldmatrix.sync.aligned.m8n8.x4.shared.b16 {%0,%1,%2,%3}, [%4];"
                 : "=r"(r[0]), "=r"(r[1]), "=r"(r[2]), "=r"(r[3]) : "r"(addr));
}
__device__ __forceinline__ void ldsm_x4_t(uint32_t* r, uint32_t addr) {
    asm volatile("ldmatrix.sync.aligned.m8n8.x4.trans.shared.b16 {%0,%1,%2,%3}, [%4];"
                 : "=r"(r[0]), "=r"(r[1]), "=r"(r[2]), "=r"(r[3]) : "r"(addr));
}
__device__ __forceinline__ void mma_bf16(float* d, const uint32_t* a, uint32_t b0, uint32_t b1) {
    asm volatile("mma.sync.aligned.m16n8k16.row.col.f32.bf16.bf16.f32 "
                 "{%0,%1,%2,%3},{%4,%5,%6,%7},{%8,%9},{%0,%1,%2,%3};"
                 : "+f"(d[0]), "+f"(d[1]), "+f"(d[2]), "+f"(d[3])
                 : "r"(a[0]), "r"(a[1]), "r"(a[2]), "r"(a[3]), "r"(b0), "r"(b1));
}

__device__ __forceinline__ void split4(float4 v, uint2& hi, uint2& lo) {
    __nv_bfloat16 hx = __float2bfloat16(v.x);
    __nv_bfloat16 hy = __float2bfloat16(v.y);
    __nv_bfloat16 hz = __float2bfloat16(v.z);
    __nv_bfloat16 hw = __float2bfloat16(v.w);
    __nv_bfloat16 lx = __float2bfloat16(v.x - __bfloat162float(hx));
    __nv_bfloat16 ly = __float2bfloat16(v.y - __bfloat162float(hy));
    __nv_bfloat16 lz = __float2bfloat16(v.z - __bfloat162float(hz));
    __nv_bfloat16 lw = __float2bfloat16(v.w - __bfloat162float(hw));
    __nv_bfloat162 h01 = __nv_bfloat162(hx, hy), h23 = __nv_bfloat162(hz, hw);
    __nv_bfloat162 l01 = __nv_bfloat162(lx, ly), l23 = __nv_bfloat162(lz, lw);
    hi.x = *reinterpret_cast<uint32_t*>(&h01);
    hi.y = *reinterpret_cast<uint32_t*>(&h23);
    lo.x = *reinterpret_cast<uint32_t*>(&l01);
    lo.y = *reinterpret_cast<uint32_t*>(&l23);
}

template <bool RELU>
__global__ __launch_bounds__(256, 1) void k_mma_gemm(
    int M, int N, int K,
    const float* __restrict__ A, const float* __restrict__ B,
    const float* __restrict__ bias, float* __restrict__ C) {
    extern __shared__ char sm_raw[];
    const uint32_t smbase = (uint32_t)__cvta_generic_to_shared(sm_raw);

    const int tid = threadIdx.x;
    const int lane = tid & 31;
    const int wid = tid >> 5;
    const int warpM = wid >> 2;     // 0..1
    const int warpN = wid & 3;      // 0..3
    const int blockM = blockIdx.y * 128;
    const int blockN = blockIdx.x * 128;

    // global load mapping
    const int aRow0 = tid >> 3;             // +32*i
    const int aCol  = (tid & 7) << 2;
    const int bRow0 = tid >> 5;             // +8*i
    const int bCol  = (tid & 31) << 2;

    float acc[4][4][4];
#pragma unroll
    for (int i = 0; i < 4; i++)
#pragma unroll
        for (int j = 0; j < 4; j++)
#pragma unroll
            for (int c = 0; c < 4; c++) acc[i][j][c] = 0.0f;

    // ldmatrix base offsets (per-lane, element units)
    const int lq = lane >> 4;               // 0/1
    const int lr = lane & 15;
    // A tiles: row = warpM*64 + im*16 + lr, col = kk + 8*lq
    // B tiles: row = kk + lr, col = warpN*32 + ip*16 + 8*lq

    float4 pa[4], pb[4];
    const int nStages = K >> 5;

    // prologue: load stage 0
#pragma unroll
    for (int i = 0; i < 4; i++) {
        int gr = blockM + aRow0 + i * 32;
        pa[i] = (gr < M) ? *reinterpret_cast<const float4*>(A + (size_t)gr * K + aCol)
                         : make_float4(0.f, 0.f, 0.f, 0.f);
        pb[i] = *reinterpret_cast<const float4*>(B + (size_t)(bRow0 + i * 8) * N + blockN + bCol);
    }
    {
        __nv_bfloat16* sm = reinterpret_cast<__nv_bfloat16*>(sm_raw);
#pragma unroll
        for (int i = 0; i < 4; i++) {
            uint2 hi, lo;
            split4(pa[i], hi, lo);
            int off = (aRow0 + i * 32) * A_STRIDE + aCol;
            *reinterpret_cast<uint2*>(sm + SM_A_HI + off) = hi;
            *reinterpret_cast<uint2*>(sm + SM_A_LO + off) = lo;
            split4(pb[i], hi, lo);
            off = (bRow0 + i * 8) * B_STRIDE + bCol;
            *reinterpret_cast<uint2*>(sm + SM_B_HI + off) = hi;
            *reinterpret_cast<uint2*>(sm + SM_B_LO + off) = lo;
        }
    }
    __syncthreads();

    for (int t = 0; t < nStages; t++) {
        // prefetch next stage into regs
        if (t + 1 < nStages) {
            int k0 = (t + 1) << 5;
#pragma unroll
            for (int i = 0; i < 4; i++) {
                int gr = blockM + aRow0 + i * 32;
                pa[i] = (gr < M) ? *reinterpret_cast<const float4*>(A + (size_t)gr * K + k0 + aCol)
                                 : make_float4(0.f, 0.f, 0.f, 0.f);
                pb[i] = *reinterpret_cast<const float4*>(B + (size_t)(k0 + bRow0 + i * 8) * N + blockN + bCol);
            }
        }

        const uint32_t stage = smbase + (uint32_t)((t & 1) * STAGE_ELTS * 2);
#pragma unroll
        for (int kk = 0; kk < 32; kk += 16) {
            uint32_t a_hi[4][4], a_lo[4][4], b_hi[2][4], b_lo[2][4];
#pragma unroll
            for (int im = 0; im < 4; im++) {
                int row = warpM * 64 + im * 16 + lr;
                int col = kk + 8 * lq;
                uint32_t addr = stage + (uint32_t)((row * A_STRIDE + col) * 2);
                ldsm_x4(a_hi[im], addr + SM_A_HI * 2);
                ldsm_x4(a_lo[im], addr + SM_A_LO * 2);
            }
#pragma unroll
            for (int ip = 0; ip < 2; ip++) {
                int row = kk + lr;
                int col = warpN * 32 + ip * 16 + 8 * lq;
                uint32_t addr = stage + (uint32_t)((row * B_STRIDE + col) * 2);
                ldsm_x4_t(b_hi[ip], addr + SM_B_HI * 2);
                ldsm_x4_t(b_lo[ip], addr + SM_B_LO * 2);
            }
#pragma unroll
            for (int im = 0; im < 4; im++) {
#pragma unroll
                for (int in = 0; in < 4; in++) {
                    int ip = in >> 1, h = (in & 1) << 1;
                    uint32_t bh0 = b_hi[ip][h], bh1 = b_hi[ip][h + 1];
                    uint32_t bl0 = b_lo[ip][h], bl1 = b_lo[ip][h + 1];
                    mma_bf16(acc[im][in], a_hi[im], bh0, bh1);
                    mma_bf16(acc[im][in], a_hi[im], bl0, bl1);
                    mma_bf16(acc[im][in], a_lo[im], bh0, bh1);
                }
            }
        }
        __syncthreads();

        // store next stage
        if (t + 1 < nStages) {
            __nv_bfloat16* sm = reinterpret_cast<__nv_bfloat16*>(
                sm_raw + ((t + 1) & 1) * STAGE_ELTS * 2);
#pragma unroll
            for (int i = 0; i < 4; i++) {
                uint2 hi, lo;
                split4(pa[i], hi, lo);
                int off = (aRow0 + i * 32) * A_STRIDE + aCol;
                *reinterpret_cast<uint2*>(sm + SM_A_HI + off) = hi;
                *reinterpret_cast<uint2*>(sm + SM_A_LO + off) = lo;
                split4(pb[i], hi, lo);
                off = (bRow0 + i * 8) * B_STRIDE + bCol;
                *reinterpret_cast<uint2*>(sm + SM_B_HI + off) = hi;
                *reinterpret_cast<uint2*>(sm + SM_B_LO + off) = lo;
            }
            __syncthreads();
        }
    }

    // epilogue
    const int g = lane >> 2, tg = lane & 3;
#pragma unroll
    for (int im = 0; im < 4; im++) {
#pragma unroll
        for (int in = 0; in < 4; in++) {
            int col = blockN + warpN * 32 + in * 8 + tg * 2;
            float b0 = bias[col], b1 = bias[col + 1];
            int row0 = blockM + warpM * 64 + im * 16 + g;
            float v0 = acc[im][in][0] + b0;
            float v1 = acc[im][in][1] + b1;
            float v2 = acc[im][in][2] + b0;
            float v3 = acc[im][in][3] + b1;
            if (RELU) {
                v0 = fmaxf(v0, 0.f); v1 = fmaxf(v1, 0.f);
                v2 = fmaxf(v2, 0.f); v3 = fmaxf(v3, 0.f);
            }
            if (row0 < M)
                *reinterpret_cast<float2*>(C + (size_t)row0 * N + col) = make_float2(v0, v1);
            if (row0 + 8 < M)
                *reinterpret_cast<float2*>(C + (size_t)(row0 + 8) * N + col) = make_float2(v2, v3);
        }
    }
}

// ---------------- K5: head ------------------------------------------------------
__global__ __launch_bounds__(256) void k_head(
    const float* __restrict__ h, const float* __restrict__ W3,
    const float* __restrict__ b3,
    float* __restrict__ out_sig, float* __restrict__ out_latent) {
    int p = blockIdx.x;
    int tid = threadIdx.x;
    int lane = tid & 31;
    int wid = tid >> 5;

    float acc[NP_DIM];
#pragma unroll
    for (int j = 0; j < NP_DIM; j++) acc[j] = 0.0f;

    const float* hrow = h + (size_t)p * H_DIM;
    for (int k = tid; k < H_DIM; k += 256) {
        float hv = hrow[k];
        const float* w = W3 + (size_t)k * NP_DIM;
#pragma unroll
        for (int j = 0; j < NP_DIM; j++) acc[j] = fmaf(hv, w[j], acc[j]);
    }
#pragma unroll
    for (int j = 0; j < NP_DIM; j++) {
#pragma unroll
        for (int s = 16; s > 0; s >>= 1)
            acc[j] += __shfl_down_sync(0xFFFFFFFF, acc[j], s);
    }
    __shared__ float smem[8][NP_DIM];
    if (lane == 0) {
#pragma unroll
        for (int j = 0; j < NP_DIM; j++) smem[wid][j] = acc[j];
    }
    __syncthreads();
    if (tid < NP_DIM) {
        float s = 0.0f;
#pragma unroll
        for (int w = 0; w < 8; w++) s += smem[w][tid];
        float latent = s + b3[tid];
        out_latent[p * NP_DIM + tid] = latent;
        out_sig[p * NP_DIM + tid] = 1.0f / (1.0f + expf(-latent));
    }
}

// ---------------- launch ----------------------------------------------------
extern "C" void kernel_launch(void* const* d_in, const int* in_sizes, int n_in,
                              void* d_out, int out_size) {
    const float* motion_z    = (const float*)d_in[0];
    const int*   tasks       = (const int*)d_in[1];
    const int*   tasks_mask  = (const int*)d_in[2];
    const int*   patient_ids = (const int*)d_in[3];
    const float* phenos      = (const float*)d_in[4];
    const int*   phenos_mask = (const int*)d_in[5];
    const float* W1          = (const float*)d_in[6];
    const float* b1          = (const float*)d_in[7];
    const float* W2          = (const float*)d_in[8];
    const float* b2          = (const float*)d_in[9];
    const float* W3          = (const float*)d_in[10];
    const float* b3          = (const float*)d_in[11];

    float* out_sig    = (float*)d_out;
    float* out_uni    = out_sig + P_DIM * NP_DIM;
    float* out_latent = out_uni + P_DIM * NP_DIM;

    float* fp;  cudaGetSymbolAddress((void**)&fp, g_fp);
    float* h1;  cudaGetSymbolAddress((void**)&h1, g_h1);
    float* h2;  cudaGetSymbolAddress((void**)&h2, g_h2);

    static bool attr_done = false;
    if (!attr_done) {
        cudaFuncSetAttribute(k_mma_gemm<true>,
                             cudaFuncAttributeMaxDynamicSharedMemorySize, SMEM_BYTES);
        attr_done = true;
    }

    k_init<<<1024, 256>>>();
    k_scatter<<<(N_TOT * 32 + 255) / 256, 256>>>(motion_z, tasks, tasks_mask,
                                                 patient_ids, phenos_mask);
    k_task_mean<<<T_DIM, 128>>>();
    k_fingerprint<<<(PT * D_DIM + 255) / 256, 256>>>();
    k_uni_phenos<<<(P_DIM * NP_DIM + 255) / 256, 256>>>(phenos, out_uni);

    // GEMM1: [2000,1024] @ [1024,2048] -> h1 (relu)
    {
        dim3 grid(H_DIM / 128, (P_DIM + 127) / 128);
        k_mma_gemm<true><<<grid, 256, SMEM_BYTES>>>(P_DIM, H_DIM, TD, fp, W1, b1, h1);
    }
    // GEMM2: [2000,2048] @ [2048,2048] -> h2 (relu)
    {
        dim3 grid(H_DIM / 128, (P_DIM + 127) / 128);
        k_mma_gemm<true><<<grid, 256, SMEM_BYTES>>>(P_DIM, H_DIM, H_DIM, h1, W2, b2, h2);
    }
    k_head<<<P_DIM, 256>>>(h2, W3, b3, out_sig, out_latent);
}

// round 3
// speedup vs baseline: 3.3712x; 1.2426x over previous
#include <cuda_runtime.h>
#include <cuda_bf16.h>
#include <math.h>
#include <stdint.h>

// Problem constants
#define N_TOT 200000
#define D_DIM 128
#define T_DIM 8
#define P_DIM 2000
#define NP_DIM 9
#define H_DIM 2048
#define PT (P_DIM * T_DIM)
#define TD (T_DIM * D_DIM)          // 1024

// ---------------- scratch ----------------------------------------------------
__device__ float g_pt_sum[PT * D_DIM];
__device__ float g_pt_cnt[PT];
__device__ float g_task_sum[TD];          // per-task column sums
__device__ float g_task_cnt[T_DIM];
__device__ int   g_first[P_DIM];
__device__ __nv_bfloat16 g_fphi[P_DIM * TD];
__device__ __nv_bfloat16 g_fplo[P_DIM * TD];
__device__ __nv_bfloat16 g_W1hi[TD * H_DIM];
__device__ __nv_bfloat16 g_W1lo[TD * H_DIM];
__device__ __nv_bfloat16 g_W2hi[H_DIM * H_DIM];
__device__ __nv_bfloat16 g_W2lo[H_DIM * H_DIM];
__device__ __nv_bfloat16 g_h1hi[P_DIM * H_DIM];
__device__ __nv_bfloat16 g_h1lo[P_DIM * H_DIM];
__device__ float g_h2[P_DIM * H_DIM];

// ---------------- helpers ------------------------------------------------------
__device__ __forceinline__ void split1(float v, __nv_bfloat16& hi, __nv_bfloat16& lo) {
    hi = __float2bfloat16(v);
    lo = __float2bfloat16(v - __bfloat162float(hi));
}
__device__ __forceinline__ void split4(float4 v, uint2& hi, uint2& lo) {
    __nv_bfloat16 hx, hy, hz, hw, lx, ly, lz, lw;
    split1(v.x, hx, lx); split1(v.y, hy, ly);
    split1(v.z, hz, lz); split1(v.w, hw, lw);
    __nv_bfloat162 h01(hx, hy), h23(hz, hw), l01(lx, ly), l23(lz, lw);
    hi.x = *reinterpret_cast<uint32_t*>(&h01);
    hi.y = *reinterpret_cast<uint32_t*>(&h23);
    lo.x = *reinterpret_cast<uint32_t*>(&l01);
    lo.y = *reinterpret_cast<uint32_t*>(&l23);
}

// ---------------- K0: init ----------------------------------------------------
__global__ void k_init() {
    int i = blockIdx.x * blockDim.x + threadIdx.x;
    int stride = gridDim.x * blockDim.x;
    for (int j = i; j < PT * D_DIM; j += stride) g_pt_sum[j] = 0.0f;
    for (int j = i; j < PT; j += stride) g_pt_cnt[j] = 0.0f;
    for (int j = i; j < TD; j += stride) g_task_sum[j] = 0.0f;
    for (int j = i; j < T_DIM; j += stride) g_task_cnt[j] = 0.0f;
    for (int j = i; j < P_DIM; j += stride) g_first[j] = N_TOT;
}

// ---------------- K1: masked scatter (one warp per row) ------------------------
__global__ void k_scatter(const float* __restrict__ motion_z,
                          const int* __restrict__ tasks,
                          const int* __restrict__ tasks_mask,
                          const int* __restrict__ patient_ids,
                          const int* __restrict__ phenos_mask) {
    int warp_id = (blockIdx.x * blockDim.x + threadIdx.x) >> 5;
    int lane = threadIdx.x & 31;
    if (warp_id >= N_TOT) return;

    int tm = tasks_mask[warp_id];
    int pm = phenos_mask[warp_id];
    if (tm != 1 || pm != 1) return;

    int t = tasks[warp_id];
    int p = patient_ids[warp_id];
    int seg = p * T_DIM + t;

    const float4* src = reinterpret_cast<const float4*>(motion_z + (size_t)warp_id * D_DIM);
    float4 v = src[lane];
    float* dst = g_pt_sum + (size_t)seg * D_DIM + lane * 4;
    atomicAdd(dst + 0, v.x);
    atomicAdd(dst + 1, v.y);
    atomicAdd(dst + 2, v.z);
    atomicAdd(dst + 3, v.w);
    if (lane == 0) {
        atomicAdd(&g_pt_cnt[seg], 1.0f);
        atomicMin(&g_first[p], warp_id);
    }
}

// ---------------- K2a: per-task counts (one block per task) --------------------
__global__ void k_task_cnt() {
    int t = blockIdx.x;
    int tid = threadIdx.x;
    float c = 0.0f;
    for (int p = tid; p < P_DIM; p += 256) c += g_pt_cnt[p * T_DIM + t];
    __shared__ float s[256];
    s[tid] = c;
    __syncthreads();
    for (int k = 128; k > 0; k >>= 1) {
        if (tid < k) s[tid] += s[tid + k];
        __syncthreads();
    }
    if (tid == 0) g_task_cnt[t] = s[0];
}

// ---------------- K2b: per-task partial sums (parallel over patients) ----------
#define TCHUNK 80
__global__ void k_task_red() {
    int t = blockIdx.x;          // 0..7
    int ch = blockIdx.y;         // 0..24
    int d = threadIdx.x;         // 0..127
    float s = 0.0f;
    int p0 = ch * TCHUNK;
#pragma unroll 4
    for (int p = p0; p < p0 + TCHUNK; p++)
        s += g_pt_sum[((size_t)p * T_DIM + t) * D_DIM + d];
    atomicAdd(&g_task_sum[t * D_DIM + d], s);
}

// ---------------- K2c: fingerprint -> split bf16 --------------------------------
__global__ void k_fingerprint() {
    int idx = blockIdx.x * blockDim.x + threadIdx.x;
    if (idx >= PT * D_DIM) return;
    int seg = idx / D_DIM;
    int d = idx - seg * D_DIM;
    int t = seg % T_DIM;
    float cnt = g_pt_cnt[seg];
    float v;
    if (cnt > 0.0f) {
        v = g_pt_sum[idx] / cnt;
    } else {
        v = g_task_sum[t * D_DIM + d] / fmaxf(g_task_cnt[t], 1.0f);
    }
    __nv_bfloat16 hi, lo;
    split1(v, hi, lo);
    g_fphi[idx] = hi;
    g_fplo[idx] = lo;
}

// ---------------- K2d: uni_phenos gather ----------------------------------------
__global__ void k_uni_phenos(const float* __restrict__ phenos, float* __restrict__ out_uni) {
    int idx = blockIdx.x * blockDim.x + threadIdx.x;
    if (idx >= P_DIM * NP_DIM) return;
    int p = idx / NP_DIM;
    int j = idx - p * NP_DIM;
    int f = g_first[p];
    if (f > N_TOT - 1) f = N_TOT - 1;
    out_uni[idx] = phenos[(size_t)f * NP_DIM + j];
}

// ---------------- K3: split weights to hi/lo bf16 -------------------------------
__global__ void k_split(const float* __restrict__ src,
                        __nv_bfloat16* __restrict__ hi,
                        __nv_bfloat16* __restrict__ lo, int n4) {
    int i = blockIdx.x * blockDim.x + threadIdx.x;
    if (i >= n4) return;
    float4 v = reinterpret_cast<const float4*>(src)[i];
    uint2 h, l;
    split4(v, h, l);
    *reinterpret_cast<uint2*>(hi + (size_t)i * 4) = h;
    *reinterpret_cast<uint2*>(lo + (size_t)i * 4) = l;
}

// =================================================================================
// Split-bf16 tensor-core GEMM with cp.async pipeline.
// A_hi/A_lo [M,K] bf16 row-major, B_hi/B_lo [K,N] bf16 row-major.
// Block tile 128x256, BK=32, 512 threads (16 warps as 2x8), warp tile 64x32.
// acc += ahi*bhi + ahi*blo + alo*bhi (fp32 acc).
// =================================================================================
#define A_STRIDE 40      // 32 data + 8 pad (bf16 elts) -> 80B rows, ldmatrix phase-clean
#define B_STRIDE 264     // 256 data + 8 pad -> 528B rows, ldmatrix.trans phase-clean
#define SM_A_HI 0
#define SM_A_LO (128 * A_STRIDE)                    // 5120
#define SM_B_HI (2 * 128 * A_STRIDE)                // 10240
#define SM_B_LO (SM_B_HI + 32 * B_STRIDE)           // 18688
#define STAGE_ELTS (SM_B_LO + 32 * B_STRIDE)        // 27136 elts
#define SMEM_BYTES (2 * STAGE_ELTS * 2)             // 108544 bytes

__device__ __forceinline__ void cp16(uint32_t dst, const void* src, bool pred) {
    int sz = pred ? 16 : 0;
    asm volatile("cp.async.cg.shared.global [%0], [%1], 16, %2;\n"
                 :: "r"(dst), "l"(src), "r"(sz));
}
__device__ __forceinline__ void cp_commit() {
    asm volatile("cp.async.commit_group;\n");
}
template <int NG>
__device__ __forceinline__ void cp_wait() {
    asm volatile("cp.async.wait_group %0;\n" :: "n"(NG));
}
__device__ __forceinline__ void ldsm_x4(uint32_t* r, uint32_t addr) {
    asm volatile("ldmatrix.sync.aligned.m8n8.x4.shared.b16 {%0,%1,%2,%3}, [%4];"
                 : "=r"(r[0]), "=r"(r[1]), "=r"(r[2]), "=r"(r[3]) : "r"(addr));
}
__device__ __forceinline__ void ldsm_x4_t(uint32_t* r, uint32_t addr) {
    asm volatile("ldmatrix.sync.aligned.m8n8.x4.trans.shared.b16 {%0,%1,%2,%3}, [%4];"
                 : "=r"(r[0]), "=r"(r[1]), "=r"(r[2]), "=r"(r[3]) : "r"(addr));
}
__device__ __forceinline__ void mma_bf16(float* d, const uint32_t* a, uint32_t b0, uint32_t b1) {
    asm volatile("mma.sync.aligned.m16n8k16.row.col.f32.bf16.bf16.f32 "
                 "{%0,%1,%2,%3},{%4,%5,%6,%7},{%8,%9},{%0,%1,%2,%3};"
                 : "+f"(d[0]), "+f"(d[1]), "+f"(d[2]), "+f"(d[3])
                 : "r"(a[0]), "r"(a[1]), "r"(a[2]), "r"(a[3]), "r"(b0), "r"(b1));
}

// stage loader: 512 threads issue 6 cp.async each
__device__ __forceinline__ void load_stage(
    uint32_t stage, const __nv_bfloat16* Ahi, const __nv_bfloat16* Alo,
    const __nv_bfloat16* Bhi, const __nv_bfloat16* Blo,
    int M, int N, int K, int blockM, int blockN, int k0, int tid) {
    // A: 128 rows x 4 chunks(16B) = 512
    int arow = tid >> 2;
    int achk = (tid & 3) << 3;                 // element offset (8 bf16 = 16B)
    int grow = blockM + arow;
    bool ap = grow < M;
    size_t goff = (size_t)grow * K + k0 + achk;
    uint32_t soff = stage + (uint32_t)((arow * A_STRIDE + achk) * 2);
    cp16(soff + SM_A_HI * 2, Ahi + goff, ap);
    cp16(soff + SM_A_LO * 2, Alo + goff, ap);
    // B: 32 rows x 32 chunks = 1024 -> 2 per thread
#pragma unroll
    for (int i = 0; i < 2; i++) {
        int idx = tid + i * 512;
        int brow = idx >> 5;
        int bchk = (idx & 31) << 3;
        size_t gb = (size_t)(k0 + brow) * N + blockN + bchk;
        uint32_t sb = stage + (uint32_t)((brow * B_STRIDE + bchk) * 2);
        cp16(sb + SM_B_HI * 2, Bhi + gb, true);
        cp16(sb + SM_B_LO * 2, Blo + gb, true);
    }
}

// OUT_MODE: 0 = fp32 relu -> C ; 1 = relu + split bf16 -> Chi/Clo
template <int OUT_MODE>
__global__ __launch_bounds__(512, 1) void k_mma_gemm(
    int M, int N, int K,
    const __nv_bfloat16* __restrict__ Ahi, const __nv_bfloat16* __restrict__ Alo,
    const __nv_bfloat16* __restrict__ Bhi, const __nv_bfloat16* __restrict__ Blo,
    const float* __restrict__ bias,
    float* __restrict__ C,
    __nv_bfloat16* __restrict__ Chi, __nv_bfloat16* __restrict__ Clo) {
    extern __shared__ char sm_raw[];
    const uint32_t smbase = (uint32_t)__cvta_generic_to_shared(sm_raw);

    const int tid = threadIdx.x;
    const int lane = tid & 31;
    const int wid = tid >> 5;
    const int warpM = wid >> 3;     // 0..1
    const int warpN = wid & 7;      // 0..7
    const int blockM = blockIdx.y * 128;
    const int blockN = blockIdx.x * 256;

    float acc[4][4][4];
#pragma unroll
    for (int i = 0; i < 4; i++)
#pragma unroll
        for (int j = 0; j < 4; j++)
#pragma unroll
            for (int c = 0; c < 4; c++) acc[i][j][c] = 0.0f;

    const int lq = lane >> 4;
    const int lr = lane & 15;
    const int nStages = K >> 5;

    // prologue
    load_stage(smbase, Ahi, Alo, Bhi, Blo, M, N, K, blockM, blockN, 0, tid);
    cp_commit();

    for (int t = 0; t < nStages; t++) {
        if (t + 1 < nStages) {
            load_stage(smbase + (uint32_t)(((t + 1) & 1) * STAGE_ELTS * 2),
                       Ahi, Alo, Bhi, Blo, M, N, K, blockM, blockN, (t + 1) << 5, tid);
            cp_commit();
            cp_wait<1>();
        } else {
            cp_wait<0>();
        }
        __syncthreads();

        const uint32_t stage = smbase + (uint32_t)((t & 1) * STAGE_ELTS * 2);
#pragma unroll
        for (int kk = 0; kk < 32; kk += 16) {
            uint32_t a_hi[4][4], a_lo[4][4], b_hi[2][4], b_lo[2][4];
#pragma unroll
            for (int im = 0; im < 4; im++) {
                int row = warpM * 64 + im * 16 + lr;
                int col = kk + 8 * lq;
                uint32_t addr = stage + (uint32_t)((row * A_STRIDE + col) * 2);
                ldsm_x4(a_hi[im], addr + SM_A_HI * 2);
                ldsm_x4(a_lo[im], addr + SM_A_LO * 2);
            }
#pragma unroll
            for (int ip = 0; ip < 2; ip++) {
                int row = kk + lr;
                int col = warpN * 32 + ip * 16 + 8 * lq;
                uint32_t addr = stage + (uint32_t)((row * B_STRIDE + col) * 2);
                ldsm_x4_t(b_hi[ip], addr + SM_B_HI * 2);
                ldsm_x4_t(b_lo[ip], addr + SM_B_LO * 2);
            }
#pragma unroll
            for (int im = 0; im < 4; im++) {
#pragma unroll
                for (int in = 0; in < 4; in++) {
                    int ip = in >> 1, h = (in & 1) << 1;
                    uint32_t bh0 = b_hi[ip][h], bh1 = b_hi[ip][h + 1];
                    uint32_t bl0 = b_lo[ip][h], bl1 = b_lo[ip][h + 1];
                    mma_bf16(acc[im][in], a_hi[im], bh0, bh1);
                    mma_bf16(acc[im][in], a_hi[im], bl0, bl1);
                    mma_bf16(acc[im][in], a_lo[im], bh0, bh1);
                }
            }
        }
        __syncthreads();
    }

    // epilogue
    const int g = lane >> 2, tg = lane & 3;
#pragma unroll
    for (int im = 0; im < 4; im++) {
#pragma unroll
        for (int in = 0; in < 4; in++) {
            int col = blockN + warpN * 32 + in * 8 + tg * 2;
            float b0 = bias[col], b1 = bias[col + 1];
            int row0 = blockM + warpM * 64 + im * 16 + g;
            float v0 = fmaxf(acc[im][in][0] + b0, 0.f);
            float v1 = fmaxf(acc[im][in][1] + b1, 0.f);
            float v2 = fmaxf(acc[im][in][2] + b0, 0.f);
            float v3 = fmaxf(acc[im][in][3] + b1, 0.f);
            if (OUT_MODE == 0) {
                if (row0 < M)
                    *reinterpret_cast<float2*>(C + (size_t)row0 * N + col) = make_float2(v0, v1);
                if (row0 + 8 < M)
                    *reinterpret_cast<float2*>(C + (size_t)(row0 + 8) * N + col) = make_float2(v2, v3);
            } else {
                __nv_bfloat16 h0, h1x, l0, l1;
                if (row0 < M) {
                    split1(v0, h0, l0); split1(v1, h1x, l1);
                    __nv_bfloat162 hh(h0, h1x), ll(l0, l1);
                    *reinterpret_cast<__nv_bfloat162*>(Chi + (size_t)row0 * N + col) = hh;
                    *reinterpret_cast<__nv_bfloat162*>(Clo + (size_t)row0 * N + col) = ll;
                }
                if (row0 + 8 < M) {
                    split1(v2, h0, l0); split1(v3, h1x, l1);
                    __nv_bfloat162 hh(h0, h1x), ll(l0, l1);
                    *reinterpret_cast<__nv_bfloat162*>(Chi + (size_t)(row0 + 8) * N + col) = hh;
                    *reinterpret_cast<__nv_bfloat162*>(Clo + (size_t)(row0 + 8) * N + col) = ll;
                }
            }
        }
    }
}

// ---------------- K5: head ------------------------------------------------------
__global__ __launch_bounds__(256) void k_head(
    const float* __restrict__ h, const float* __restrict__ W3,
    const float* __restrict__ b3,
    float* __restrict__ out_sig, float* __restrict__ out_latent) {
    int p = blockIdx.x;
    int tid = threadIdx.x;
    int lane = tid & 31;
    int wid = tid >> 5;

    float acc[NP_DIM];
#pragma unroll
    for (int j = 0; j < NP_DIM; j++) acc[j] = 0.0f;

    const float* hrow = h + (size_t)p * H_DIM;
    for (int k = tid; k < H_DIM; k += 256) {
        float hv = hrow[k];
        const float* w = W3 + (size_t)k * NP_DIM;
#pragma unroll
        for (int j = 0; j < NP_DIM; j++) acc[j] = fmaf(hv, w[j], acc[j]);
    }
#pragma unroll
    for (int j = 0; j < NP_DIM; j++) {
#pragma unroll
        for (int s = 16; s > 0; s >>= 1)
            acc[j] += __shfl_down_sync(0xFFFFFFFF, acc[j], s);
    }
    __shared__ float smem[8][NP_DIM];
    if (lane == 0) {
#pragma unroll
        for (int j = 0; j < NP_DIM; j++) smem[wid][j] = acc[j];
    }
    __syncthreads();
    if (tid < NP_DIM) {
        float s = 0.0f;
#pragma unroll
        for (int w = 0; w < 8; w++) s += smem[w][tid];
        float latent = s + b3[tid];
        out_latent[p * NP_DIM + tid] = latent;
        out_sig[p * NP_DIM + tid] = 1.0f / (1.0f + expf(-latent));
    }
}

// ---------------- launch ----------------------------------------------------
extern "C" void kernel_launch(void* const* d_in, const int* in_sizes, int n_in,
                              void* d_out, int out_size) {
    const float* motion_z    = (const float*)d_in[0];
    const int*   tasks       = (const int*)d_in[1];
    const int*   tasks_mask  = (const int*)d_in[2];
    const int*   patient_ids = (const int*)d_in[3];
    const float* phenos      = (const float*)d_in[4];
    const int*   phenos_mask = (const int*)d_in[5];
    const float* W1          = (const float*)d_in[6];
    const float* b1          = (const float*)d_in[7];
    const float* W2          = (const float*)d_in[8];
    const float* b2          = (const float*)d_in[9];
    const float* W3          = (const float*)d_in[10];
    const float* b3          = (const float*)d_in[11];

    float* out_sig    = (float*)d_out;
    float* out_uni    = out_sig + P_DIM * NP_DIM;
    float* out_latent = out_uni + P_DIM * NP_DIM;

    __nv_bfloat16 *fphi, *fplo, *w1hi, *w1lo, *w2hi, *w2lo, *h1hi, *h1lo;
    float* h2;
    cudaGetSymbolAddress((void**)&fphi, g_fphi);
    cudaGetSymbolAddress((void**)&fplo, g_fplo);
    cudaGetSymbolAddress((void**)&w1hi, g_W1hi);
    cudaGetSymbolAddress((void**)&w1lo, g_W1lo);
    cudaGetSymbolAddress((void**)&w2hi, g_W2hi);
    cudaGetSymbolAddress((void**)&w2lo, g_W2lo);
    cudaGetSymbolAddress((void**)&h1hi, g_h1hi);
    cudaGetSymbolAddress((void**)&h1lo, g_h1lo);
    cudaGetSymbolAddress((void**)&h2, g_h2);

    cudaFuncSetAttribute(k_mma_gemm<0>, cudaFuncAttributeMaxDynamicSharedMemorySize, SMEM_BYTES);
    cudaFuncSetAttribute(k_mma_gemm<1>, cudaFuncAttributeMaxDynamicSharedMemorySize, SMEM_BYTES);

    k_init<<<1024, 256>>>();
    k_scatter<<<(N_TOT * 32 + 255) / 256, 256>>>(motion_z, tasks, tasks_mask,
                                                 patient_ids, phenos_mask);
    k_task_cnt<<<T_DIM, 256>>>();
    {
        dim3 grid(T_DIM, P_DIM / TCHUNK);   // 8 x 25
        k_task_red<<<grid, 128>>>();
    }
    k_fingerprint<<<(PT * D_DIM + 255) / 256, 256>>>();
    k_uni_phenos<<<(P_DIM * NP_DIM + 255) / 256, 256>>>(phenos, out_uni);

    // split weights
    k_split<<<(TD * H_DIM / 4 + 255) / 256, 256>>>(W1, w1hi, w1lo, TD * H_DIM / 4);
    k_split<<<(H_DIM * H_DIM / 4 + 255) / 256, 256>>>(W2, w2hi, w2lo, H_DIM * H_DIM / 4);

    // GEMM1: [2000,1024] @ [1024,2048] -> h1 (relu, split bf16 out)
    {
        dim3 grid(H_DIM / 256, (P_DIM + 127) / 128);   // 8 x 16
        k_mma_gemm<1><<<grid, 512, SMEM_BYTES>>>(P_DIM, H_DIM, TD,
                                                 fphi, fplo, w1hi, w1lo, b1,
                                                 nullptr, h1hi, h1lo);
    }
    // GEMM2: [2000,2048] @ [2048,2048] -> h2 (relu, fp32 out)
    {
        dim3 grid(H_DIM / 256, (P_DIM + 127) / 128);
        k_mma_gemm<0><<<grid, 512, SMEM_BYTES>>>(P_DIM, H_DIM, H_DIM,
                                                 h1hi, h1lo, w2hi, w2lo, b2,
                                                 h2, nullptr, nullptr);
    }
    k_head<<<P_DIM, 256>>>(h2, W3, b3, out_sig, out_latent);
}